// round 1
// baseline (speedup 1.0000x reference)
#include <cuda_runtime.h>

#define Bc   2
#define Lc   512
#define DIMc 128
#define Kc   32
#define EPSc 1e-5f

// Scratch (no allocs allowed): 6 x 512KB = 3MB, fits easily in L2 for the big kernel.
__device__ float g_out_mean[Bc * Lc * DIMc];
__device__ float g_in_mean [Bc * Lc * DIMc];
__device__ float g_out_agg [Bc * Lc * DIMc];
__device__ float g_in_agg  [Bc * Lc * DIMc];
__device__ float g_go      [Bc * Lc * DIMc];
__device__ float g_gi      [Bc * Lc * DIMc];

// Kernel 1: gather-means along both axes.
// blockIdx.x = b*L + r  (r is "i" for out_mean and "j" for in_mean), thread = d.
__global__ void means_kernel(const float* __restrict__ pair) {
    const int rr = blockIdx.x;        // b*L + r
    const int b  = rr / Lc;
    const int r  = rr % Lc;
    const int d  = threadIdx.x;       // 0..127

    float so = 0.f, si = 0.f;
    #pragma unroll
    for (int k = 0; k < Kc; k++) {
        const int idx = (k * (Lc - 1)) / (Kc - 1);   // exact floor(linspace)
        so += pair[((size_t)rr * Lc + idx) * DIMc + d];              // pair[b, r, idx, d]
        si += pair[(((size_t)b * Lc + idx) * Lc + r) * DIMc + d];    // pair[b, idx, r, d]
    }
    g_out_mean[rr * DIMc + d] = so * (1.f / Kc);
    g_in_mean [rr * DIMc + d] = si * (1.f / Kc);
}

// Kernel 2: small row-major GEMM  Out[r,d] = sum_m A[r,m]*W[m,d] (+ bias[d]).
// 8 rows per block so W (64KB) is read once per 8 rows (L2-resident anyway).
#define RPB 8
__global__ void gemm_kernel(const float* __restrict__ A,
                            const float* __restrict__ W,
                            const float* __restrict__ bias,
                            float* __restrict__ Out) {
    __shared__ float sA[RPB][DIMc];
    const int d  = threadIdx.x;
    const int r0 = blockIdx.x * RPB;
    #pragma unroll
    for (int r = 0; r < RPB; r++)
        sA[r][d] = A[(r0 + r) * DIMc + d];
    __syncthreads();

    float acc[RPB];
    const float bv = bias ? bias[d] : 0.f;
    #pragma unroll
    for (int r = 0; r < RPB; r++) acc[r] = bv;

    for (int m = 0; m < DIMc; m++) {
        const float w = W[m * DIMc + d];      // coalesced; broadcast sA[r][m]
        #pragma unroll
        for (int r = 0; r < RPB; r++)
            acc[r] = fmaf(sA[r][m], w, acc[r]);
    }
    #pragma unroll
    for (int r = 0; r < RPB; r++)
        Out[(r0 + r) * DIMc + d] = acc[r];
}

// Kernel 3: fused gate/update/blend + LayerNorm. One warp per (b,i,j) row,
// one float4 per lane (128 elems). Streams 256MB in + 256MB out.
__global__ void __launch_bounds__(256) fuse_ln_kernel(
    const float* __restrict__ pair,
    const float* __restrict__ b_g,
    const float* __restrict__ ln_w,
    const float* __restrict__ ln_b,
    float* __restrict__ out)
{
    const int warp = threadIdx.x >> 5;
    const int lane = threadIdx.x & 31;
    const size_t row = (size_t)blockIdx.x * 8 + warp;   // 0 .. B*L*L-1
    const int bi = (int)(row / Lc);                     // b*L + i
    const int j  = (int)(row % Lc);
    const int b  = bi / Lc;
    const int bj = b * Lc + j;

    const float4* __restrict__ p4 = (const float4*)pair;
    const float4 p  = p4[row * 32 + lane];
    const float4 oa = ((const float4*)g_out_agg)[bi * 32 + lane];
    const float4 ia = ((const float4*)g_in_agg )[bj * 32 + lane];
    const float4 go = ((const float4*)g_go     )[bi * 32 + lane];
    const float4 gi = ((const float4*)g_gi     )[bj * 32 + lane];
    const float4 bg = ((const float4*)b_g )[lane];

    float x0, x1, x2, x3;
    {
        float z, g, u;
        z = go.x + gi.x + bg.x; g = 1.f / (1.f + __expf(-z));
        u = oa.x + ia.x;        x0 = fmaf(g, u - p.x, p.x);
        z = go.y + gi.y + bg.y; g = 1.f / (1.f + __expf(-z));
        u = oa.y + ia.y;        x1 = fmaf(g, u - p.y, p.y);
        z = go.z + gi.z + bg.z; g = 1.f / (1.f + __expf(-z));
        u = oa.z + ia.z;        x2 = fmaf(g, u - p.z, p.z);
        z = go.w + gi.w + bg.w; g = 1.f / (1.f + __expf(-z));
        u = oa.w + ia.w;        x3 = fmaf(g, u - p.w, p.w);
    }

    float s  = x0 + x1 + x2 + x3;
    float sq = x0*x0 + x1*x1 + x2*x2 + x3*x3;
    #pragma unroll
    for (int o = 16; o; o >>= 1) {
        s  += __shfl_xor_sync(0xFFFFFFFFu, s,  o);
        sq += __shfl_xor_sync(0xFFFFFFFFu, sq, o);
    }
    const float mean = s * (1.f / DIMc);
    const float var  = sq * (1.f / DIMc) - mean * mean;
    const float rstd = rsqrtf(var + EPSc);

    const float4 lw = ((const float4*)ln_w)[lane];
    const float4 lb = ((const float4*)ln_b)[lane];

    float4 o4;
    o4.x = fmaf((x0 - mean) * rstd, lw.x, lb.x);
    o4.y = fmaf((x1 - mean) * rstd, lw.y, lb.y);
    o4.z = fmaf((x2 - mean) * rstd, lw.z, lb.z);
    o4.w = fmaf((x3 - mean) * rstd, lw.w, lb.w);
    ((float4*)out)[row * 32 + lane] = o4;
}

extern "C" void kernel_launch(void* const* d_in, const int* in_sizes, int n_in,
                              void* d_out, int out_size) {
    const float* pair  = (const float*)d_in[0];
    const float* W_out = (const float*)d_in[1];
    const float* b_out = (const float*)d_in[2];
    const float* W_in  = (const float*)d_in[3];
    const float* b_in  = (const float*)d_in[4];
    const float* W_g   = (const float*)d_in[5];
    const float* b_g   = (const float*)d_in[6];
    const float* ln_w  = (const float*)d_in[7];
    const float* ln_b  = (const float*)d_in[8];
    float* out = (float*)d_out;

    float *p_om, *p_im, *p_oa, *p_ia, *p_go, *p_gi;
    cudaGetSymbolAddress((void**)&p_om, g_out_mean);
    cudaGetSymbolAddress((void**)&p_im, g_in_mean);
    cudaGetSymbolAddress((void**)&p_oa, g_out_agg);
    cudaGetSymbolAddress((void**)&p_ia, g_in_agg);
    cudaGetSymbolAddress((void**)&p_go, g_go);
    cudaGetSymbolAddress((void**)&p_gi, g_gi);

    // 1) gather means
    means_kernel<<<Bc * Lc, DIMc>>>(pair);
    // 2) four tiny GEMMs (chained deps handled by stream order)
    gemm_kernel<<<(Bc * Lc) / RPB, DIMc>>>(p_om, W_out, b_out, p_oa);
    gemm_kernel<<<(Bc * Lc) / RPB, DIMc>>>(p_im, W_in,  b_in,  p_ia);
    gemm_kernel<<<(Bc * Lc) / RPB, DIMc>>>(p_oa, W_g,                 nullptr, p_go);
    gemm_kernel<<<(Bc * Lc) / RPB, DIMc>>>(p_ia, W_g + DIMc * DIMc,   nullptr, p_gi);
    // 3) fused gate + blend + LayerNorm (the 512MB streamer)
    fuse_ln_kernel<<<(Bc * Lc * Lc) / 8, 256>>>(pair, b_g, ln_w, ln_b, out);
}

// round 3
// speedup vs baseline: 1.0744x; 1.0744x over previous
#include <cuda_runtime.h>

#define Bc   2
#define Lc   512
#define DIMc 128
#define Kc   32
#define EPSc 1e-5f
#define RPA  4      // rows per block in the small-GEMM kernels
#define TI   16     // fuse tile (i)
#define TJ   16     // fuse tile (j)

// Scratch (no allocs allowed): 4 x 512KB = 2MB, L2-resident.
__device__ float g_out_agg[Bc * Lc * DIMc];
__device__ float g_in_agg [Bc * Lc * DIMc];
__device__ float g_go     [Bc * Lc * DIMc];  // out_agg @ Wg_o + b_g
__device__ float g_gi     [Bc * Lc * DIMc];  // in_agg  @ Wg_i

// ---------------------------------------------------------------------------
// Kernel 1: gather-means + both agg GEMMs fused.
// Block handles RPA global rows (b*L + r). Means live in smem, then each
// thread d computes oa/ia for its column over all RPA rows.
// ---------------------------------------------------------------------------
__global__ void __launch_bounds__(DIMc) meansagg_kernel(
    const float* __restrict__ pair,
    const float* __restrict__ W_out, const float* __restrict__ b_out,
    const float* __restrict__ W_in,  const float* __restrict__ b_in)
{
    __shared__ float som[RPA][DIMc];
    __shared__ float sim[RPA][DIMc];
    const int d  = threadIdx.x;
    const int r0 = blockIdx.x * RPA;          // global row (b*L + r)
    const int b  = r0 >> 9;

    #pragma unroll
    for (int r = 0; r < RPA; r++) {
        const int rr = r0 + r;
        const int rl = rr & (Lc - 1);
        float so = 0.f, si = 0.f;
        #pragma unroll
        for (int k = 0; k < Kc; k++) {
            const int idx = (k * (Lc - 1)) / (Kc - 1);   // exact floor(linspace)
            so += pair[((size_t)rr * Lc + idx) * DIMc + d];             // [b,r,idx,d]
            si += pair[(((size_t)b * Lc + idx) * Lc + rl) * DIMc + d];  // [b,idx,r,d]
        }
        som[r][d] = so * (1.f / Kc);
        sim[r][d] = si * (1.f / Kc);
    }
    __syncthreads();

    float ao[RPA], ai[RPA];
    const float bo = b_out[d], bi = b_in[d];
    #pragma unroll
    for (int r = 0; r < RPA; r++) { ao[r] = bo; ai[r] = bi; }

    #pragma unroll 8
    for (int m = 0; m < DIMc; m++) {
        const float wo = W_out[m * DIMc + d];
        const float wi = W_in [m * DIMc + d];
        #pragma unroll
        for (int r = 0; r < RPA; r++) {
            ao[r] = fmaf(som[r][m], wo, ao[r]);
            ai[r] = fmaf(sim[r][m], wi, ai[r]);
        }
    }
    #pragma unroll
    for (int r = 0; r < RPA; r++) {
        g_out_agg[(r0 + r) * DIMc + d] = ao[r];
        g_in_agg [(r0 + r) * DIMc + d] = ai[r];
    }
}

// ---------------------------------------------------------------------------
// Kernel 2: dual gate projection. First half of grid: go = oa@Wg_o + b_g.
// Second half: gi = ia@Wg_i (bias folded into go only).
// ---------------------------------------------------------------------------
__global__ void __launch_bounds__(DIMc) gate_kernel(const float* __restrict__ W_g,
                                                    const float* __restrict__ b_g)
{
    __shared__ float sA[RPA][DIMc];
    const int d = threadIdx.x;
    const int half = (Bc * Lc) / RPA;                 // 256
    const bool second = blockIdx.x >= half;
    const int  blk = second ? blockIdx.x - half : blockIdx.x;
    const float* __restrict__ A = second ? g_in_agg : g_out_agg;
    const float* __restrict__ W = second ? (W_g + DIMc * DIMc) : W_g;
    float* __restrict__ O = second ? g_gi : g_go;
    const int r0 = blk * RPA;

    #pragma unroll
    for (int r = 0; r < RPA; r++)
        sA[r][d] = A[(r0 + r) * DIMc + d];
    __syncthreads();

    float acc[RPA];
    const float bv = second ? 0.f : b_g[d];
    #pragma unroll
    for (int r = 0; r < RPA; r++) acc[r] = bv;

    #pragma unroll 8
    for (int m = 0; m < DIMc; m++) {
        const float w = W[m * DIMc + d];
        #pragma unroll
        for (int r = 0; r < RPA; r++)
            acc[r] = fmaf(sA[r][m], w, acc[r]);
    }
    #pragma unroll
    for (int r = 0; r < RPA; r++)
        O[(r0 + r) * DIMc + d] = acc[r];
}

// ---------------------------------------------------------------------------
// Kernel 3: fused gate/blend + LayerNorm, tiled 16i x 16j so the broadcast
// rows (oa/go/ia/gi) hit smem instead of hammering L2. One warp per row,
// 2 rows per loop iteration for MLP=2 on the 512B pair loads.
// ---------------------------------------------------------------------------
__device__ __forceinline__ void row_compute(
    const float4 p, const float4 OA, const float4 IA,
    const float4 GO, const float4 GI,
    const float4 lw, const float4 lb, float4& o4)
{
    float x0, x1, x2, x3;
    {
        float z, g, u;
        z = GO.x + GI.x; g = 1.f / (1.f + __expf(-z));
        u = OA.x + IA.x; x0 = fmaf(g, u - p.x, p.x);
        z = GO.y + GI.y; g = 1.f / (1.f + __expf(-z));
        u = OA.y + IA.y; x1 = fmaf(g, u - p.y, p.y);
        z = GO.z + GI.z; g = 1.f / (1.f + __expf(-z));
        u = OA.z + IA.z; x2 = fmaf(g, u - p.z, p.z);
        z = GO.w + GI.w; g = 1.f / (1.f + __expf(-z));
        u = OA.w + IA.w; x3 = fmaf(g, u - p.w, p.w);
    }
    float s  = x0 + x1 + x2 + x3;
    float sq = x0*x0 + x1*x1 + x2*x2 + x3*x3;
    #pragma unroll
    for (int o = 16; o; o >>= 1) {
        s  += __shfl_xor_sync(0xFFFFFFFFu, s,  o);
        sq += __shfl_xor_sync(0xFFFFFFFFu, sq, o);
    }
    const float mean = s * (1.f / DIMc);
    const float var  = sq * (1.f / DIMc) - mean * mean;
    const float rstd = rsqrtf(var + EPSc);
    o4.x = fmaf((x0 - mean) * rstd, lw.x, lb.x);
    o4.y = fmaf((x1 - mean) * rstd, lw.y, lb.y);
    o4.z = fmaf((x2 - mean) * rstd, lw.z, lb.z);
    o4.w = fmaf((x3 - mean) * rstd, lw.w, lb.w);
}

__global__ void __launch_bounds__(256) fuse_ln_kernel(
    const float* __restrict__ pair,
    const float* __restrict__ ln_w,
    const float* __restrict__ ln_b,
    float* __restrict__ out)
{
    __shared__ float4 s_oa[TI][32];
    __shared__ float4 s_go[TI][32];
    __shared__ float4 s_ia[TJ][32];
    __shared__ float4 s_gi[TJ][32];

    const int t    = threadIdx.x;
    const int tile = blockIdx.x;              // b*1024 + ti*32 + tj
    const int b    = tile >> 10;
    const int ti   = (tile >> 5) & 31;
    const int tj   = tile & 31;
    const int i0   = ti * TI, j0 = tj * TJ;

    const float4* __restrict__ oa4 = (const float4*)g_out_agg;
    const float4* __restrict__ go4 = (const float4*)g_go;
    const float4* __restrict__ ia4 = (const float4*)g_in_agg;
    const float4* __restrict__ gi4 = (const float4*)g_gi;

    #pragma unroll
    for (int s = t; s < TI * 32; s += 256) {
        const int row = s >> 5, c = s & 31;
        s_oa[row][c] = oa4[(b * Lc + i0 + row) * 32 + c];
        s_go[row][c] = go4[(b * Lc + i0 + row) * 32 + c];
        s_ia[row][c] = ia4[(b * Lc + j0 + row) * 32 + c];
        s_gi[row][c] = gi4[(b * Lc + j0 + row) * 32 + c];
    }
    __syncthreads();

    const int warp = t >> 5, lane = t & 31;
    const float4 lw = ((const float4*)ln_w)[lane];
    const float4 lb = ((const float4*)ln_b)[lane];
    const float4* __restrict__ p4 = (const float4*)pair;
    float4* __restrict__ o4p = (float4*)out;

    // warp handles 32 of the 256 tile rows; 2 rows per iter for load MLP.
    #pragma unroll 1
    for (int tt = 0; tt < 32; tt += 2) {
        const int ra = warp * 32 + tt;
        const int rb = ra + 1;
        const int lia = ra >> 4, lja = ra & 15;
        const int lib = rb >> 4, ljb = rb & 15;
        const size_t growa = ((size_t)(b * Lc + i0 + lia) * Lc + (j0 + lja));
        const size_t growb = ((size_t)(b * Lc + i0 + lib) * Lc + (j0 + ljb));
        const float4 pa = p4[growa * 32 + lane];
        const float4 pb = p4[growb * 32 + lane];

        float4 oA;
        row_compute(pa, s_oa[lia][lane], s_ia[lja][lane],
                        s_go[lia][lane], s_gi[lja][lane], lw, lb, oA);
        o4p[growa * 32 + lane] = oA;

        float4 oB;
        row_compute(pb, s_oa[lib][lane], s_ia[ljb][lane],
                        s_go[lib][lane], s_gi[ljb][lane], lw, lb, oB);
        o4p[growb * 32 + lane] = oB;
    }
}

extern "C" void kernel_launch(void* const* d_in, const int* in_sizes, int n_in,
                              void* d_out, int out_size) {
    const float* pair  = (const float*)d_in[0];
    const float* W_out = (const float*)d_in[1];
    const float* b_out = (const float*)d_in[2];
    const float* W_in  = (const float*)d_in[3];
    const float* b_in  = (const float*)d_in[4];
    const float* W_g   = (const float*)d_in[5];
    const float* b_g   = (const float*)d_in[6];
    const float* ln_w  = (const float*)d_in[7];
    const float* ln_b  = (const float*)d_in[8];
    float* out = (float*)d_out;

    meansagg_kernel<<<(Bc * Lc) / RPA, DIMc>>>(pair, W_out, b_out, W_in, b_in);
    gate_kernel<<<2 * (Bc * Lc) / RPA, DIMc>>>(W_g, b_g);
    fuse_ln_kernel<<<Bc * (Lc / TI) * (Lc / TJ), 256>>>(pair, ln_w, ln_b, out);
}

// round 6
// speedup vs baseline: 1.1910x; 1.1086x over previous
#include <cuda_runtime.h>

#define Bc   2
#define Lc   512
#define DIMc 128
#define Kc   32
#define EPSc 1e-5f
#define RPB  4      // rows per block in the front kernel
#define FTI  8      // fuse: i-rows per block (one per warp)
#define FTJ  32     // fuse: j-rows per block (smem tile)

// Scratch: 4 x 512KB = 2MB, L2-resident.
__device__ float g_out_agg[Bc * Lc * DIMc];
__device__ float g_in_agg [Bc * Lc * DIMc];
__device__ float g_go     [Bc * Lc * DIMc];  // out_agg @ Wg_o + b_g
__device__ float g_gi     [Bc * Lc * DIMc];  // in_agg  @ Wg_i

__device__ __forceinline__ float tanh_approx(float x) {
    float r;
    asm("tanh.approx.f32 %0, %1;" : "=f"(r) : "f"(x));
    return r;
}

// ---------------------------------------------------------------------------
// Kernel 1: entire front-end. Per block: RPB rows. 256 threads:
//   d = t&127 (output column), h = t>>7 (k-half for means / role for GEMVs).
// means (k-split) -> agg GEMVs (oa | ia) -> gate GEMVs (go | gi).
// ---------------------------------------------------------------------------
__global__ void __launch_bounds__(256) front_kernel(
    const float* __restrict__ pair,
    const float* __restrict__ W_out, const float* __restrict__ b_out,
    const float* __restrict__ W_in,  const float* __restrict__ b_in,
    const float* __restrict__ W_g,   const float* __restrict__ b_g)
{
    __shared__ float s_om[2][RPB][DIMc];   // partials, then [0] holds mean
    __shared__ float s_im[2][RPB][DIMc];
    __shared__ float s_a [2][RPB][DIMc];   // [0]=oa, [1]=ia

    const int t  = threadIdx.x;
    const int d  = t & 127;
    const int h  = t >> 7;                 // 0 or 1
    const int r0 = blockIdx.x * RPB;
    const int b  = r0 >> 9;

    // --- means, k-split 2-way, many independent loads/thread ---
    float so[RPB], si[RPB];
    #pragma unroll
    for (int r = 0; r < RPB; r++) { so[r] = 0.f; si[r] = 0.f; }

    #pragma unroll
    for (int kk = 0; kk < Kc / 2; kk++) {
        const int k   = h * (Kc / 2) + kk;
        const int idx = (k * (Lc - 1)) / (Kc - 1);
        #pragma unroll
        for (int r = 0; r < RPB; r++) {
            const int rr = r0 + r;
            const int rl = rr & (Lc - 1);
            so[r] += pair[((size_t)rr * Lc + idx) * DIMc + d];
            si[r] += pair[(((size_t)b * Lc + idx) * Lc + rl) * DIMc + d];
        }
    }
    #pragma unroll
    for (int r = 0; r < RPB; r++) {
        s_om[h][r][d] = so[r];
        s_im[h][r][d] = si[r];
    }
    __syncthreads();
    // combine halves into [0] and scale by 1/K
    for (int s = t; s < RPB * DIMc; s += 256) {
        const int r = s >> 7, dd = s & 127;
        s_om[0][r][dd] = (s_om[0][r][dd] + s_om[1][r][dd]) * (1.f / Kc);
        s_im[0][r][dd] = (s_im[0][r][dd] + s_im[1][r][dd]) * (1.f / Kc);
    }
    __syncthreads();

    // --- agg GEMVs: h==0 -> oa (W_out), h==1 -> ia (W_in) ---
    {
        const float* __restrict__ W   = h ? W_in : W_out;
        const float (*src)[DIMc]      = h ? s_im[0] : s_om[0];
        float* __restrict__ dst       = h ? g_in_agg : g_out_agg;
        float acc[RPB];
        const float bv = h ? b_in[d] : b_out[d];
        #pragma unroll
        for (int r = 0; r < RPB; r++) acc[r] = bv;
        #pragma unroll 8
        for (int m = 0; m < DIMc; m++) {
            const float w = W[m * DIMc + d];
            #pragma unroll
            for (int r = 0; r < RPB; r++)
                acc[r] = fmaf(src[r][m], w, acc[r]);
        }
        #pragma unroll
        for (int r = 0; r < RPB; r++) {
            dst[(r0 + r) * DIMc + d] = acc[r];
            s_a[h][r][d] = acc[r];
        }
    }
    __syncthreads();

    // --- gate GEMVs: h==0 -> go = oa@Wg_o + b_g, h==1 -> gi = ia@Wg_i ---
    {
        const float* __restrict__ W = W_g + h * DIMc * DIMc;
        float* __restrict__ dst     = h ? g_gi : g_go;
        float acc[RPB];
        const float bv = h ? 0.f : b_g[d];
        #pragma unroll
        for (int r = 0; r < RPB; r++) acc[r] = bv;
        #pragma unroll 8
        for (int m = 0; m < DIMc; m++) {
            const float w = W[m * DIMc + d];
            #pragma unroll
            for (int r = 0; r < RPB; r++)
                acc[r] = fmaf(s_a[h][r][m], w, acc[r]);
        }
        #pragma unroll
        for (int r = 0; r < RPB; r++)
            dst[(r0 + r) * DIMc + d] = acc[r];
    }
}

// ---------------------------------------------------------------------------
// Kernel 2: fused gate/blend + LayerNorm.
// Block = 8 i-rows (one per warp) x 32 j-rows (smem). Warp keeps oa/go for
// its i in registers; ia/gi come from smem; ILP=4 j-rows per iteration so
// the shfl-butterfly latencies of 4 independent rows overlap.
// ---------------------------------------------------------------------------
__device__ __forceinline__ float4 row_compute(
    const float4 p, const float4 OA, const float4 IA,
    const float4 GO, const float4 GI,
    const float4 lw, const float4 lb)
{
    float x0, x1, x2, x3;
    {
        float z, g, u;
        z = GO.x + GI.x; g = fmaf(0.5f, tanh_approx(0.5f * z), 0.5f);
        u = OA.x + IA.x; x0 = fmaf(g, u - p.x, p.x);
        z = GO.y + GI.y; g = fmaf(0.5f, tanh_approx(0.5f * z), 0.5f);
        u = OA.y + IA.y; x1 = fmaf(g, u - p.y, p.y);
        z = GO.z + GI.z; g = fmaf(0.5f, tanh_approx(0.5f * z), 0.5f);
        u = OA.z + IA.z; x2 = fmaf(g, u - p.z, p.z);
        z = GO.w + GI.w; g = fmaf(0.5f, tanh_approx(0.5f * z), 0.5f);
        u = OA.w + IA.w; x3 = fmaf(g, u - p.w, p.w);
    }
    float s  = x0 + x1 + x2 + x3;
    float sq = x0*x0 + x1*x1 + x2*x2 + x3*x3;
    #pragma unroll
    for (int o = 16; o; o >>= 1) {
        s  += __shfl_xor_sync(0xFFFFFFFFu, s,  o);
        sq += __shfl_xor_sync(0xFFFFFFFFu, sq, o);
    }
    const float mean = s * (1.f / DIMc);
    const float var  = sq * (1.f / DIMc) - mean * mean;
    const float rstd = rsqrtf(var + EPSc);
    float4 o;
    o.x = fmaf((x0 - mean) * rstd, lw.x, lb.x);
    o.y = fmaf((x1 - mean) * rstd, lw.y, lb.y);
    o.z = fmaf((x2 - mean) * rstd, lw.z, lb.z);
    o.w = fmaf((x3 - mean) * rstd, lw.w, lb.w);
    return o;
}

__global__ void __launch_bounds__(256) fuse_ln_kernel(
    const float* __restrict__ pair,
    const float* __restrict__ ln_w,
    const float* __restrict__ ln_b,
    float* __restrict__ out)
{
    __shared__ float4 s_ia[FTJ][32];
    __shared__ float4 s_gi[FTJ][32];

    const int t    = threadIdx.x;
    const int tile = blockIdx.x;             // b*(64*16) + it*16 + jt
    const int b    = tile >> 10;
    const int it   = (tile >> 4) & 63;
    const int jt   = tile & 15;
    const int i0   = it * FTI, j0 = jt * FTJ;

    const float4* __restrict__ ia4 = (const float4*)g_in_agg;
    const float4* __restrict__ gi4 = (const float4*)g_gi;

    #pragma unroll
    for (int s = t; s < FTJ * 32; s += 256) {
        const int row = s >> 5, c = s & 31;
        s_ia[row][c] = ia4[(b * Lc + j0 + row) * 32 + c];
        s_gi[row][c] = gi4[(b * Lc + j0 + row) * 32 + c];
    }
    __syncthreads();

    const int warp = t >> 5, lane = t & 31;
    const int bi = b * Lc + i0 + warp;       // this warp's i-row

    const float4 oa = ((const float4*)g_out_agg)[bi * 32 + lane];
    const float4 go = ((const float4*)g_go     )[bi * 32 + lane];
    const float4 lw = ((const float4*)ln_w)[lane];
    const float4 lb = ((const float4*)ln_b)[lane];

    const float4* __restrict__ p4 = (const float4*)pair;
    float4* __restrict__ o4p = (float4*)out;
    const size_t rowbase = ((size_t)bi * Lc + j0) * 32 + lane;

    #pragma unroll 1
    for (int jj = 0; jj < FTJ; jj += 4) {
        float4 p[4];
        #pragma unroll
        for (int u = 0; u < 4; u++)
            p[u] = __ldcs(&p4[rowbase + (size_t)(jj + u) * 32]);

        #pragma unroll
        for (int u = 0; u < 4; u++) {
            const float4 o = row_compute(p[u], oa, s_ia[jj + u][lane],
                                         go, s_gi[jj + u][lane], lw, lb);
            __stcs(&o4p[rowbase + (size_t)(jj + u) * 32], o);
        }
    }
}

extern "C" void kernel_launch(void* const* d_in, const int* in_sizes, int n_in,
                              void* d_out, int out_size) {
    const float* pair  = (const float*)d_in[0];
    const float* W_out = (const float*)d_in[1];
    const float* b_out = (const float*)d_in[2];
    const float* W_in  = (const float*)d_in[3];
    const float* b_in  = (const float*)d_in[4];
    const float* W_g   = (const float*)d_in[5];
    const float* b_g   = (const float*)d_in[6];
    const float* ln_w  = (const float*)d_in[7];
    const float* ln_b  = (const float*)d_in[8];
    float* out = (float*)d_out;

    front_kernel<<<(Bc * Lc) / RPB, 256>>>(pair, W_out, b_out, W_in, b_in, W_g, b_g);
    fuse_ln_kernel<<<Bc * (Lc / FTI) * (Lc / FTJ), 256>>>(pair, ln_w, ln_b, out);
}

// round 7
// speedup vs baseline: 1.6554x; 1.3899x over previous
#include <cuda_runtime.h>

#define Bc   2
#define Lc   512
#define DIMc 128
#define Kc   32
#define EPSc 1e-5f
#define RPB  4      // rows per block in the GEMV kernel
#define FTI  8      // fuse: i-rows per block (one per warp)
#define FTJ  32     // fuse: j-rows per block (smem tile)

// Scratch: 6 x 512KB = 3MB, L2-resident.
__device__ float g_out_mean[Bc * Lc * DIMc];
__device__ float g_in_mean [Bc * Lc * DIMc];
__device__ float g_out_agg [Bc * Lc * DIMc];
__device__ float g_in_agg  [Bc * Lc * DIMc];
__device__ float g_go      [Bc * Lc * DIMc];  // out_agg @ Wg_o + b_g
__device__ float g_gi      [Bc * Lc * DIMc];  // in_agg  @ Wg_i

__device__ __forceinline__ float tanh_approx(float x) {
    float r;
    asm("tanh.approx.f32 %0, %1;" : "=f"(r) : "f"(x));
    return r;
}

// ---------------------------------------------------------------------------
// Kernel 1: gather-means. One block per global row (b*L + r), 256 threads:
// d = t&127, h = t>>7 (k-half). 32 independent DRAM loads per thread.
// ---------------------------------------------------------------------------
__global__ void __launch_bounds__(256) means_kernel(const float* __restrict__ pair)
{
    __shared__ float sm[2][2][DIMc];   // [arr][h][d]
    const int rr = blockIdx.x;         // b*L + r
    const int b  = rr >> 9;
    const int rl = rr & (Lc - 1);
    const int t  = threadIdx.x;
    const int d  = t & 127;
    const int h  = t >> 7;

    float so = 0.f, si = 0.f;
    #pragma unroll
    for (int kk = 0; kk < Kc / 2; kk++) {
        const int k   = h * (Kc / 2) + kk;
        const int idx = (k * (Lc - 1)) / (Kc - 1);   // exact floor(linspace)
        so += pair[((size_t)rr * Lc + idx) * DIMc + d];             // [b,r,idx,d]
        si += pair[(((size_t)b * Lc + idx) * Lc + rl) * DIMc + d];  // [b,idx,r,d]
    }
    sm[0][h][d] = so;
    sm[1][h][d] = si;
    __syncthreads();
    if (h == 0) {
        g_out_mean[rr * DIMc + d] = (sm[0][0][d] + sm[0][1][d]) * (1.f / Kc);
        g_in_mean [rr * DIMc + d] = (sm[1][0][d] + sm[1][1][d]) * (1.f / Kc);
    }
}

// ---------------------------------------------------------------------------
// Kernel 2: agg GEMVs + gate GEMVs chained through smem.
// 256 threads: d = t&127, h = t>>7 selects (oa,W_out)|(ia,W_in) then (go)|(gi).
// ---------------------------------------------------------------------------
__global__ void __launch_bounds__(256) agg_gate_kernel(
    const float* __restrict__ W_out, const float* __restrict__ b_out,
    const float* __restrict__ W_in,  const float* __restrict__ b_in,
    const float* __restrict__ W_g,   const float* __restrict__ b_g)
{
    __shared__ float s_om[RPB][DIMc];
    __shared__ float s_im[RPB][DIMc];
    __shared__ float s_a [2][RPB][DIMc];   // [0]=oa, [1]=ia

    const int t  = threadIdx.x;
    const int d  = t & 127;
    const int h  = t >> 7;
    const int r0 = blockIdx.x * RPB;

    for (int s = t; s < RPB * DIMc; s += 256) {
        const int r = s >> 7, dd = s & 127;
        s_om[r][dd] = g_out_mean[(r0 + r) * DIMc + dd];
        s_im[r][dd] = g_in_mean [(r0 + r) * DIMc + dd];
    }
    __syncthreads();

    // agg GEMVs
    {
        const float* __restrict__ W = h ? W_in : W_out;
        const float (*src)[DIMc]    = h ? s_im : s_om;
        float* __restrict__ dst     = h ? g_in_agg : g_out_agg;
        float acc[RPB];
        const float bv = h ? b_in[d] : b_out[d];
        #pragma unroll
        for (int r = 0; r < RPB; r++) acc[r] = bv;
        #pragma unroll 8
        for (int m = 0; m < DIMc; m++) {
            const float w = W[m * DIMc + d];
            #pragma unroll
            for (int r = 0; r < RPB; r++)
                acc[r] = fmaf(src[r][m], w, acc[r]);
        }
        #pragma unroll
        for (int r = 0; r < RPB; r++) {
            dst[(r0 + r) * DIMc + d] = acc[r];
            s_a[h][r][d] = acc[r];
        }
    }
    __syncthreads();

    // gate GEMVs: go = oa@Wg_o + b_g ; gi = ia@Wg_i
    {
        const float* __restrict__ W = W_g + h * DIMc * DIMc;
        float* __restrict__ dst     = h ? g_gi : g_go;
        float acc[RPB];
        const float bv = h ? 0.f : b_g[d];
        #pragma unroll
        for (int r = 0; r < RPB; r++) acc[r] = bv;
        #pragma unroll 8
        for (int m = 0; m < DIMc; m++) {
            const float w = W[m * DIMc + d];
            #pragma unroll
            for (int r = 0; r < RPB; r++)
                acc[r] = fmaf(s_a[h][r][m], w, acc[r]);
        }
        #pragma unroll
        for (int r = 0; r < RPB; r++)
            dst[(r0 + r) * DIMc + d] = acc[r];
    }
}

// ---------------------------------------------------------------------------
// Kernel 3: fused gate/blend + LayerNorm. 16 lanes per row, 2 rows per warp:
// 4-level shfl butterfly amortized over 2 rows (SHFL cost 4/row vs 10/row).
// Warp owns one i-row (oa/go in regs, 8 floats/lane); ia/gi from smem.
// ---------------------------------------------------------------------------
__device__ __forceinline__ void blend4(
    const float4 p, const float4 OA, const float4 IA,
    const float4 GO, const float4 GI, float* x)
{
    float z, g, u;
    z = GO.x + GI.x; g = fmaf(0.5f, tanh_approx(0.5f * z), 0.5f);
    u = OA.x + IA.x; x[0] = fmaf(g, u - p.x, p.x);
    z = GO.y + GI.y; g = fmaf(0.5f, tanh_approx(0.5f * z), 0.5f);
    u = OA.y + IA.y; x[1] = fmaf(g, u - p.y, p.y);
    z = GO.z + GI.z; g = fmaf(0.5f, tanh_approx(0.5f * z), 0.5f);
    u = OA.z + IA.z; x[2] = fmaf(g, u - p.z, p.z);
    z = GO.w + GI.w; g = fmaf(0.5f, tanh_approx(0.5f * z), 0.5f);
    u = OA.w + IA.w; x[3] = fmaf(g, u - p.w, p.w);
}

__global__ void __launch_bounds__(256) fuse_ln_kernel(
    const float* __restrict__ pair,
    const float* __restrict__ ln_w,
    const float* __restrict__ ln_b,
    float* __restrict__ out)
{
    __shared__ float s_ia[FTJ][DIMc];
    __shared__ float s_gi[FTJ][DIMc];

    const int t    = threadIdx.x;
    const int tile = blockIdx.x;             // b*(64*16) + it*16 + jt
    const int b    = tile >> 10;
    const int it   = (tile >> 4) & 63;
    const int jt   = tile & 15;
    const int i0   = it * FTI, j0 = jt * FTJ;

    const float4* __restrict__ ia4 = (const float4*)g_in_agg;
    const float4* __restrict__ gi4 = (const float4*)g_gi;

    #pragma unroll
    for (int s = t; s < FTJ * 32; s += 256) {
        const int row = s >> 5, c = s & 31;
        ((float4*)s_ia[row])[c] = ia4[(b * Lc + j0 + row) * 32 + c];
        ((float4*)s_gi[row])[c] = gi4[(b * Lc + j0 + row) * 32 + c];
    }
    __syncthreads();

    const int warp = t >> 5;
    const int lane = t & 31;
    const int grp  = lane >> 4;   // which of the 2 j's this lane serves
    const int lr   = lane & 15;   // position within the row (covers 8 floats)
    const int bi   = b * Lc + i0 + warp;

    const float4* __restrict__ oa4 = (const float4*)g_out_agg;
    const float4* __restrict__ go4 = (const float4*)g_go;
    const float4 oa0 = oa4[bi * 32 + lr * 2];
    const float4 oa1 = oa4[bi * 32 + lr * 2 + 1];
    const float4 go0 = go4[bi * 32 + lr * 2];
    const float4 go1 = go4[bi * 32 + lr * 2 + 1];
    const float4 lw0 = ((const float4*)ln_w)[lr * 2];
    const float4 lw1 = ((const float4*)ln_w)[lr * 2 + 1];
    const float4 lb0 = ((const float4*)ln_b)[lr * 2];
    const float4 lb1 = ((const float4*)ln_b)[lr * 2 + 1];

    const float4* __restrict__ p4 = (const float4*)pair;
    float4* __restrict__ o4p = (float4*)out;
    const size_t base = ((size_t)bi * Lc + j0) * 32 + lr * 2;

    #pragma unroll 1
    for (int jj = 0; jj < FTJ; jj += 4) {
        const int jA = jj + grp;          // rows {jj, jj+1} across the warp
        const int jB = jj + 2 + grp;      // rows {jj+2, jj+3}
        const size_t offA = base + (size_t)jA * 32;
        const size_t offB = base + (size_t)jB * 32;

        const float4 pA0 = __ldcs(&p4[offA]);
        const float4 pA1 = __ldcs(&p4[offA + 1]);
        const float4 pB0 = __ldcs(&p4[offB]);
        const float4 pB1 = __ldcs(&p4[offB + 1]);

        // --- row A ---
        {
            const float4 ia0 = ((const float4*)s_ia[jA])[lr * 2];
            const float4 ia1 = ((const float4*)s_ia[jA])[lr * 2 + 1];
            const float4 gi0 = ((const float4*)s_gi[jA])[lr * 2];
            const float4 gi1 = ((const float4*)s_gi[jA])[lr * 2 + 1];
            float x[8];
            blend4(pA0, oa0, ia0, go0, gi0, x);
            blend4(pA1, oa1, ia1, go1, gi1, x + 4);
            float s = 0.f, sq = 0.f;
            #pragma unroll
            for (int e = 0; e < 8; e++) { s += x[e]; sq = fmaf(x[e], x[e], sq); }
            #pragma unroll
            for (int o = 8; o; o >>= 1) {
                s  += __shfl_xor_sync(0xFFFFFFFFu, s,  o);
                sq += __shfl_xor_sync(0xFFFFFFFFu, sq, o);
            }
            const float mean = s * (1.f / DIMc);
            const float rstd = rsqrtf(sq * (1.f / DIMc) - mean * mean + EPSc);
            float4 o0, o1;
            o0.x = fmaf((x[0] - mean) * rstd, lw0.x, lb0.x);
            o0.y = fmaf((x[1] - mean) * rstd, lw0.y, lb0.y);
            o0.z = fmaf((x[2] - mean) * rstd, lw0.z, lb0.z);
            o0.w = fmaf((x[3] - mean) * rstd, lw0.w, lb0.w);
            o1.x = fmaf((x[4] - mean) * rstd, lw1.x, lb1.x);
            o1.y = fmaf((x[5] - mean) * rstd, lw1.y, lb1.y);
            o1.z = fmaf((x[6] - mean) * rstd, lw1.z, lb1.z);
            o1.w = fmaf((x[7] - mean) * rstd, lw1.w, lb1.w);
            __stcs(&o4p[offA], o0);
            __stcs(&o4p[offA + 1], o1);
        }
        // --- row B ---
        {
            const float4 ia0 = ((const float4*)s_ia[jB])[lr * 2];
            const float4 ia1 = ((const float4*)s_ia[jB])[lr * 2 + 1];
            const float4 gi0 = ((const float4*)s_gi[jB])[lr * 2];
            const float4 gi1 = ((const float4*)s_gi[jB])[lr * 2 + 1];
            float x[8];
            blend4(pB0, oa0, ia0, go0, gi0, x);
            blend4(pB1, oa1, ia1, go1, gi1, x + 4);
            float s = 0.f, sq = 0.f;
            #pragma unroll
            for (int e = 0; e < 8; e++) { s += x[e]; sq = fmaf(x[e], x[e], sq); }
            #pragma unroll
            for (int o = 8; o; o >>= 1) {
                s  += __shfl_xor_sync(0xFFFFFFFFu, s,  o);
                sq += __shfl_xor_sync(0xFFFFFFFFu, sq, o);
            }
            const float mean = s * (1.f / DIMc);
            const float rstd = rsqrtf(sq * (1.f / DIMc) - mean * mean + EPSc);
            float4 o0, o1;
            o0.x = fmaf((x[0] - mean) * rstd, lw0.x, lb0.x);
            o0.y = fmaf((x[1] - mean) * rstd, lw0.y, lb0.y);
            o0.z = fmaf((x[2] - mean) * rstd, lw0.z, lb0.z);
            o0.w = fmaf((x[3] - mean) * rstd, lw0.w, lb0.w);
            o1.x = fmaf((x[4] - mean) * rstd, lw1.x, lb1.x);
            o1.y = fmaf((x[5] - mean) * rstd, lw1.y, lb1.y);
            o1.z = fmaf((x[6] - mean) * rstd, lw1.z, lb1.z);
            o1.w = fmaf((x[7] - mean) * rstd, lw1.w, lb1.w);
            __stcs(&o4p[offB], o0);
            __stcs(&o4p[offB + 1], o1);
        }
    }
}

extern "C" void kernel_launch(void* const* d_in, const int* in_sizes, int n_in,
                              void* d_out, int out_size) {
    const float* pair  = (const float*)d_in[0];
    const float* W_out = (const float*)d_in[1];
    const float* b_out = (const float*)d_in[2];
    const float* W_in  = (const float*)d_in[3];
    const float* b_in  = (const float*)d_in[4];
    const float* W_g   = (const float*)d_in[5];
    const float* b_g   = (const float*)d_in[6];
    const float* ln_w  = (const float*)d_in[7];
    const float* ln_b  = (const float*)d_in[8];
    float* out = (float*)d_out;

    means_kernel<<<Bc * Lc, 256>>>(pair);
    agg_gate_kernel<<<(Bc * Lc) / RPB, 256>>>(W_out, b_out, W_in, b_in, W_g, b_g);
    fuse_ln_kernel<<<Bc * (Lc / FTI) * (Lc / FTJ), 256>>>(pair, ln_w, ln_b, out);
}